// round 5
// baseline (speedup 1.0000x reference)
#include <cuda_runtime.h>
#include <cuda_bf16.h>
#include <cstdint>
#include <cstddef>

// Problem constants
#define T_SEQ 2048
#define D_MODEL 3584
#define HQ 28
#define HKV 4
#define DH 128
#define QKV_N 4608          // (HQ + 2*HKV) * DH
#define K_OFF 3584          // HQ*DH
#define V_OFF 4096          // (HQ+HKV)*DH

// Scratch (allocation-free rule: __device__ globals)
__device__ float g_qkv[(size_t)T_SEQ * QKV_N];   // 37.7 MB
__device__ float g_attn[(size_t)T_SEQ * D_MODEL]; // 29.4 MB

// ---------------------------------------------------------------------------
// Classic SGEMM: C[M,N] = A[M,K] @ B[K,N] (+ bias), all row-major fp32.
// BM=BN=128, BK=8, 256 threads, 8x8 per thread.
// ---------------------------------------------------------------------------
__global__ __launch_bounds__(256) void sgemm_kernel(
    const float* __restrict__ A, const float* __restrict__ B,
    const float* __restrict__ bias, float* __restrict__ C,
    int M, int N, int K)
{
    __shared__ __align__(16) float As[8 * 128];
    __shared__ __align__(16) float Bs[8 * 128];

    const int bx = blockIdx.x;   // N tile
    const int by = blockIdx.y;   // M tile
    const int tid = threadIdx.x;
    const int tc = tid & 15;     // 0..15 -> col group
    const int tr = tid >> 4;     // 0..15 -> row group

    const int a_r = tid >> 1;          // 0..127
    const int a_c = (tid & 1) * 4;     // 0 or 4
    const int b_r = tid >> 5;          // 0..7
    const int b_c = (tid & 31) * 4;    // 0..124

    const float* Ab = A + (size_t)(by * 128 + a_r) * K + a_c;
    const float* Bb = B + (size_t)b_r * N + bx * 128 + b_c;

    float acc[8][8];
#pragma unroll
    for (int i = 0; i < 8; ++i)
#pragma unroll
        for (int j = 0; j < 8; ++j) acc[i][j] = 0.f;

    for (int k0 = 0; k0 < K; k0 += 8) {
        float4 av = *(const float4*)(Ab + k0);
        float4 bv = *(const float4*)(Bb + (size_t)k0 * N);
        As[(a_c + 0) * 128 + a_r] = av.x;
        As[(a_c + 1) * 128 + a_r] = av.y;
        As[(a_c + 2) * 128 + a_r] = av.z;
        As[(a_c + 3) * 128 + a_r] = av.w;
        *(float4*)&Bs[b_r * 128 + b_c] = bv;
        __syncthreads();

#pragma unroll
        for (int k = 0; k < 8; ++k) {
            float am[8], bn[8];
            *(float4*)&am[0] = *(const float4*)&As[k * 128 + tr * 8];
            *(float4*)&am[4] = *(const float4*)&As[k * 128 + tr * 8 + 4];
            *(float4*)&bn[0] = *(const float4*)&Bs[k * 128 + tc * 8];
            *(float4*)&bn[4] = *(const float4*)&Bs[k * 128 + tc * 8 + 4];
#pragma unroll
            for (int i = 0; i < 8; ++i)
#pragma unroll
                for (int j = 0; j < 8; ++j)
                    acc[i][j] += am[i] * bn[j];
        }
        __syncthreads();
    }

    float bvals[8];
    if (bias) {
#pragma unroll
        for (int j = 0; j < 8; ++j)
            bvals[j] = bias[bx * 128 + tc * 8 + j];
    } else {
#pragma unroll
        for (int j = 0; j < 8; ++j) bvals[j] = 0.f;
    }

#pragma unroll
    for (int i = 0; i < 8; ++i) {
        int row = by * 128 + tr * 8 + i;
        float* Cp = C + (size_t)row * N + bx * 128 + tc * 8;
        float4 r0 = make_float4(acc[i][0] + bvals[0], acc[i][1] + bvals[1],
                                acc[i][2] + bvals[2], acc[i][3] + bvals[3]);
        float4 r1 = make_float4(acc[i][4] + bvals[4], acc[i][5] + bvals[5],
                                acc[i][6] + bvals[6], acc[i][7] + bvals[7]);
        *(float4*)(Cp) = r0;
        *(float4*)(Cp + 4) = r1;
    }
}

// ---------------------------------------------------------------------------
// RoPE: in-place on q (heads 0..27) and k (heads 28..31) of g_qkv.
// One thread per (t, head, j<64).
// ---------------------------------------------------------------------------
__global__ __launch_bounds__(256) void rope_kernel(const int* __restrict__ pos,
                                                   float* __restrict__ qkv)
{
    int idx = blockIdx.x * 256 + threadIdx.x;   // T * 32 * 64 total
    int j = idx & 63;
    int h = (idx >> 6) & 31;
    int t = idx >> 11;
    if (t >= T_SEQ) return;

    // inv_freq = 1e6^(-j/64) = exp(-j/64 * ln(1e6))
    float inv_freq = expf(-13.815510557964274f * (float)j * (1.0f / 64.0f));
    float ang = (float)pos[t] * inv_freq;
    float s, c;
    sincosf(ang, &s, &c);

    size_t base;
    if (h < HQ) base = (size_t)t * QKV_N + (size_t)h * DH;
    else        base = (size_t)t * QKV_N + K_OFF + (size_t)(h - HQ) * DH;

    float x1 = qkv[base + j];
    float x2 = qkv[base + 64 + j];
    qkv[base + j]      = x1 * c - x2 * s;
    qkv[base + 64 + j] = x2 * c + x1 * s;
}

// ---------------------------------------------------------------------------
// Flash attention, fp32, causal, GQA (group 7).
// Block: 256 threads = 16x16 grid (tx, ty). Q tile 64 rows, K tile 64 cols.
// Each thread: S frag 4x4 (rows 4ty+i, cols 4tx+j), O frag 4x8 (cols tx*8+d).
// Row softmax stats reduced across tx via shfl (16-lane groups inside warps).
// ---------------------------------------------------------------------------
#define FBM 64
#define FBN 64
#define QS_PAD 68   // row stride for transposed Q/K and for P (keeps float4 align)
#define FLASH_SMEM_FLOATS (128 * QS_PAD * 2 + FBN * DH + FBM * QS_PAD)
#define FLASH_SMEM_BYTES (FLASH_SMEM_FLOATS * 4)

__global__ __launch_bounds__(256) void flash_kernel(const float* __restrict__ qkv,
                                                    float* __restrict__ attn)
{
    extern __shared__ float sm[];
    float* Qs = sm;                       // [DH][QS_PAD] transposed: Qs[k][m]
    float* Ks = Qs + 128 * QS_PAD;        // [DH][QS_PAD] transposed: Ks[k][r]
    float* Vs = Ks + 128 * QS_PAD;        // [FBN][DH]
    float* Ps = Vs + FBN * DH;            // [FBM][QS_PAD]

    const int qt = blockIdx.x;            // 0..31
    const int h = blockIdx.y;             // 0..27
    const int hkv = h / 7;
    const int tid = threadIdx.x;
    const int tx = tid & 15;
    const int ty = tid >> 4;
    const float scale = 0.08838834764831845f;  // 1/sqrt(128)

    // Load Q tile transposed
    for (int idx = tid; idx < FBM * 32; idx += 256) {
        int m = idx >> 5;
        int k4 = (idx & 31) << 2;
        float4 v = *(const float4*)&qkv[(size_t)(qt * FBM + m) * QKV_N + h * DH + k4];
        Qs[(k4 + 0) * QS_PAD + m] = v.x;
        Qs[(k4 + 1) * QS_PAD + m] = v.y;
        Qs[(k4 + 2) * QS_PAD + m] = v.z;
        Qs[(k4 + 3) * QS_PAD + m] = v.w;
    }

    float o[4][8];
    float mrow[4], lrow[4];
#pragma unroll
    for (int i = 0; i < 4; ++i) {
        mrow[i] = -1e30f;
        lrow[i] = 0.f;
#pragma unroll
        for (int d = 0; d < 8; ++d) o[i][d] = 0.f;
    }

    for (int kt = 0; kt <= qt; ++kt) {
        __syncthreads();   // protect Ks/Vs (and Ps) from previous iteration readers
        // Load K (transposed) and V tiles
        for (int idx = tid; idx < FBN * 32; idx += 256) {
            int r = idx >> 5;
            int k4 = (idx & 31) << 2;
            size_t base = (size_t)(kt * FBN + r) * QKV_N;
            float4 kv = *(const float4*)&qkv[base + K_OFF + hkv * DH + k4];
            Ks[(k4 + 0) * QS_PAD + r] = kv.x;
            Ks[(k4 + 1) * QS_PAD + r] = kv.y;
            Ks[(k4 + 2) * QS_PAD + r] = kv.z;
            Ks[(k4 + 3) * QS_PAD + r] = kv.w;
            float4 vv = *(const float4*)&qkv[base + V_OFF + hkv * DH + k4];
            *(float4*)&Vs[r * DH + k4] = vv;
        }
        __syncthreads();

        // S = Q K^T (64x64), outer product over dh
        float s[4][4];
#pragma unroll
        for (int i = 0; i < 4; ++i)
#pragma unroll
            for (int j = 0; j < 4; ++j) s[i][j] = 0.f;

        for (int k = 0; k < DH; ++k) {
            float4 a = *(const float4*)&Qs[k * QS_PAD + 4 * ty];
            float4 b = *(const float4*)&Ks[k * QS_PAD + 4 * tx];
            float av[4] = {a.x, a.y, a.z, a.w};
            float bv[4] = {b.x, b.y, b.z, b.w};
#pragma unroll
            for (int i = 0; i < 4; ++i)
#pragma unroll
                for (int j = 0; j < 4; ++j)
                    s[i][j] += av[i] * bv[j];
        }

        const bool diag = (kt == qt);
#pragma unroll
        for (int i = 0; i < 4; ++i)
#pragma unroll
            for (int j = 0; j < 4; ++j) {
                float v = s[i][j] * scale;
                if (diag && (4 * tx + j) > (4 * ty + i)) v = -1e30f;
                s[i][j] = v;
            }

        // Online softmax per row (reduce across tx = 16-lane groups)
#pragma unroll
        for (int i = 0; i < 4; ++i) {
            float mx = fmaxf(fmaxf(s[i][0], s[i][1]), fmaxf(s[i][2], s[i][3]));
#pragma unroll
            for (int off = 1; off < 16; off <<= 1)
                mx = fmaxf(mx, __shfl_xor_sync(0xffffffffu, mx, off));
            float mn = fmaxf(mrow[i], mx);
            float corr = __expf(mrow[i] - mn);
            mrow[i] = mn;
            float rs = 0.f;
#pragma unroll
            for (int j = 0; j < 4; ++j) {
                float p = __expf(s[i][j] - mn);
                s[i][j] = p;
                rs += p;
            }
#pragma unroll
            for (int off = 1; off < 16; off <<= 1)
                rs += __shfl_xor_sync(0xffffffffu, rs, off);
            lrow[i] = lrow[i] * corr + rs;
#pragma unroll
            for (int d = 0; d < 8; ++d) o[i][d] *= corr;
            *(float4*)&Ps[(4 * ty + i) * QS_PAD + 4 * tx] =
                make_float4(s[i][0], s[i][1], s[i][2], s[i][3]);
        }
        __syncthreads();

        // O += P @ V
        for (int kp = 0; kp < FBN; ++kp) {
            float4 v0 = *(const float4*)&Vs[kp * DH + tx * 8];
            float4 v1 = *(const float4*)&Vs[kp * DH + tx * 8 + 4];
#pragma unroll
            for (int i = 0; i < 4; ++i) {
                float p = Ps[(4 * ty + i) * QS_PAD + kp];
                o[i][0] += p * v0.x;
                o[i][1] += p * v0.y;
                o[i][2] += p * v0.z;
                o[i][3] += p * v0.w;
                o[i][4] += p * v1.x;
                o[i][5] += p * v1.y;
                o[i][6] += p * v1.z;
                o[i][7] += p * v1.w;
            }
        }
    }

    // Epilogue: normalize and store to attn[T, HQ*DH]
#pragma unroll
    for (int i = 0; i < 4; ++i) {
        float inv = 1.f / lrow[i];
        int row = qt * FBM + 4 * ty + i;
        float* op = attn + (size_t)row * D_MODEL + h * DH + tx * 8;
        float4 r0 = make_float4(o[i][0] * inv, o[i][1] * inv, o[i][2] * inv, o[i][3] * inv);
        float4 r1 = make_float4(o[i][4] * inv, o[i][5] * inv, o[i][6] * inv, o[i][7] * inv);
        *(float4*)(op) = r0;
        *(float4*)(op + 4) = r1;
    }
}

// ---------------------------------------------------------------------------
extern "C" void kernel_launch(void* const* d_in, const int* in_sizes, int n_in,
                              void* d_out, int out_size)
{
    const int* positions   = (const int*)d_in[0];
    const float* hidden    = (const float*)d_in[1];
    const float* Wqkv      = (const float*)d_in[2];
    const float* bqkv      = (const float*)d_in[3];
    const float* Wo        = (const float*)d_in[4];
    float* out = (float*)d_out;

    float* qkv = nullptr;
    float* attn = nullptr;
    cudaGetSymbolAddress((void**)&qkv, g_qkv);
    cudaGetSymbolAddress((void**)&attn, g_attn);

    cudaFuncSetAttribute(flash_kernel,
                         cudaFuncAttributeMaxDynamicSharedMemorySize,
                         FLASH_SMEM_BYTES);

    // 1) QKV = hidden @ W_qkv + b
    sgemm_kernel<<<dim3(QKV_N / 128, T_SEQ / 128), 256>>>(
        hidden, Wqkv, bqkv, qkv, T_SEQ, QKV_N, D_MODEL);

    // 2) RoPE on q and k heads
    rope_kernel<<<(T_SEQ * 32 * 64) / 256, 256>>>(positions, qkv);

    // 3) Causal GQA flash attention
    flash_kernel<<<dim3(T_SEQ / FBM, HQ), 256, FLASH_SMEM_BYTES>>>(qkv, attn);

    // 4) out = attn @ W_o
    sgemm_kernel<<<dim3(D_MODEL / 128, T_SEQ / 128), 256>>>(
        attn, Wo, nullptr, out, T_SEQ, D_MODEL, D_MODEL);
}